// round 3
// baseline (speedup 1.0000x reference)
#include <cuda_runtime.h>
#include <cuda_bf16.h>
#include <cstdint>

// Chamfer distance via exact uniform-grid nearest neighbor.
// Pipeline: bbox -> per-cell histogram -> prefix scan -> scatter (cell-sorted,
// preprocessed float4 {-2x,-2y,-2z,|p|^2}) -> ring-search query kernel ->
// deterministic reduce. Exactness: after scanning the Chebyshev-radius-r cell
// cube around the query, every unscanned point is >= r*cs_min away; expand
// until best_d <= r*cs_min.

#define NPTS    16384
#define G       32
#define NC      (G * G * G)

typedef unsigned int u32;

// ---------------- scratch (__device__ globals; no allocs) ----------------
__device__ u32    g_bbox[6];                // flipped-uint: min x,y,z ; max x,y,z
__device__ int    g_counts[2][NC];
__device__ int    g_starts[2][NC + 1];
__device__ int    g_cursor[2][NC];
__device__ float4 g_sorted[2][NPTS];        // cell-sorted, preprocessed
__device__ float  g_dmin[2 * NPTS];

// ---------------- helpers ----------------
__device__ __forceinline__ u32 flip_enc(float x) {
    u32 u = __float_as_uint(x);
    return u ^ ((u & 0x80000000u) ? 0xFFFFFFFFu : 0x80000000u);
}
__device__ __forceinline__ float flip_dec(u32 u) {
    u ^= (u & 0x80000000u) ? 0x80000000u : 0xFFFFFFFFu;
    return __uint_as_float(u);
}

struct Box { float lox, loy, loz, icx, icy, icz, csmin; };

__device__ __forceinline__ Box load_box() {
    Box b;
    b.lox = flip_dec(g_bbox[0]);
    b.loy = flip_dec(g_bbox[1]);
    b.loz = flip_dec(g_bbox[2]);
    float ex = fmaxf(flip_dec(g_bbox[3]) - b.lox, 1e-6f);
    float ey = fmaxf(flip_dec(g_bbox[4]) - b.loy, 1e-6f);
    float ez = fmaxf(flip_dec(g_bbox[5]) - b.loz, 1e-6f);
    float csx = ex / G, csy = ey / G, csz = ez / G;
    b.icx = 1.0f / csx; b.icy = 1.0f / csy; b.icz = 1.0f / csz;
    b.csmin = fminf(csx, fminf(csy, csz));
    return b;
}
__device__ __forceinline__ int clampi(int v, int lo, int hi) {
    return v < lo ? lo : (v > hi ? hi : v);
}
__device__ __forceinline__ int cell1(float v, float lo, float ic) {
    return clampi((int)floorf((v - lo) * ic), 0, G - 1);
}

// ---------------- kernels ----------------
__global__ void cd_init_kernel() {
    int i = blockIdx.x * blockDim.x + threadIdx.x;
    if (i < 2 * NC) ((int*)g_counts)[i] = 0;
    if (i < 3)      g_bbox[i] = 0xFFFFFFFFu;         // min sentinel
    else if (i < 6) g_bbox[i] = 0u;                  // max sentinel
}

__global__ __launch_bounds__(256)
void cd_bbox_kernel(const float* __restrict__ gt, const float* __restrict__ gen) {
    __shared__ u32 smn[3][8], smx[3][8];
    int t = blockIdx.x * blockDim.x + threadIdx.x;   // 0 .. 2*NPTS-1
    const float* p = (t < NPTS) ? (gt + 3 * t) : (gen + 3 * (t - NPTS));
    u32 ex = flip_enc(p[0]), ey = flip_enc(p[1]), ez = flip_enc(p[2]);
    // warp reduce
#pragma unroll
    for (int s = 16; s > 0; s >>= 1) {
        ex = min(ex, __shfl_xor_sync(0xFFFFFFFFu, ex, s));
        ey = min(ey, __shfl_xor_sync(0xFFFFFFFFu, ey, s));
        ez = min(ez, __shfl_xor_sync(0xFFFFFFFFu, ez, s));
    }
    u32 mx = flip_enc(p[0]), my = flip_enc(p[1]), mz = flip_enc(p[2]);
#pragma unroll
    for (int s = 16; s > 0; s >>= 1) {
        mx = max(mx, __shfl_xor_sync(0xFFFFFFFFu, mx, s));
        my = max(my, __shfl_xor_sync(0xFFFFFFFFu, my, s));
        mz = max(mz, __shfl_xor_sync(0xFFFFFFFFu, mz, s));
    }
    int wid = threadIdx.x >> 5, lid = threadIdx.x & 31;
    if (lid == 0) {
        smn[0][wid] = ex; smn[1][wid] = ey; smn[2][wid] = ez;
        smx[0][wid] = mx; smx[1][wid] = my; smx[2][wid] = mz;
    }
    __syncthreads();
    if (threadIdx.x < 3) {
        u32 a = 0xFFFFFFFFu, b = 0u;
#pragma unroll
        for (int w = 0; w < 8; w++) { a = min(a, smn[threadIdx.x][w]); b = max(b, smx[threadIdx.x][w]); }
        atomicMin(&g_bbox[threadIdx.x], a);
        atomicMax(&g_bbox[threadIdx.x + 3], b);
    }
}

__global__ __launch_bounds__(256)
void cd_hist_kernel(const float* __restrict__ gt, const float* __restrict__ gen) {
    Box bx = load_box();
    int t = blockIdx.x * blockDim.x + threadIdx.x;
    int cloud = t >> 14, i = t & (NPTS - 1);
    const float* p = (cloud == 0 ? gt : gen) + 3 * i;
    int cx = cell1(p[0], bx.lox, bx.icx);
    int cy = cell1(p[1], bx.loy, bx.icy);
    int cz = cell1(p[2], bx.loz, bx.icz);
    atomicAdd(&g_counts[cloud][(cz * G + cy) * G + cx], 1);
}

__global__ __launch_bounds__(1024)
void cd_scan_kernel() {
    // one CTA per cloud; 1024 threads x 32 cells each
    __shared__ int part[1024];
    const int cloud = blockIdx.x;
    const int tid = threadIdx.x;
    const int base = tid * (NC / 1024);
    int s = 0;
#pragma unroll
    for (int i = 0; i < NC / 1024; i++) s += g_counts[cloud][base + i];
    part[tid] = s;
    __syncthreads();
    // Hillis-Steele inclusive scan
    for (int st = 1; st < 1024; st <<= 1) {
        int v = (tid >= st) ? part[tid - st] : 0;
        __syncthreads();
        part[tid] += v;
        __syncthreads();
    }
    int run = (tid == 0) ? 0 : part[tid - 1];     // exclusive prefix of chunk
#pragma unroll
    for (int i = 0; i < NC / 1024; i++) {
        g_starts[cloud][base + i] = run;
        g_cursor[cloud][base + i] = run;
        run += g_counts[cloud][base + i];
    }
    if (tid == 1023) g_starts[cloud][NC] = run;   // == NPTS
}

__global__ __launch_bounds__(256)
void cd_scatter_kernel(const float* __restrict__ gt, const float* __restrict__ gen) {
    Box bx = load_box();
    int t = blockIdx.x * blockDim.x + threadIdx.x;
    int cloud = t >> 14, i = t & (NPTS - 1);
    const float* p = (cloud == 0 ? gt : gen) + 3 * i;
    float x = p[0], y = p[1], z = p[2];
    int cx = cell1(x, bx.lox, bx.icx);
    int cy = cell1(y, bx.loy, bx.icy);
    int cz = cell1(z, bx.loz, bx.icz);
    int pos = atomicAdd(&g_cursor[cloud][(cz * G + cy) * G + cx], 1);
    g_sorted[cloud][pos] = make_float4(-2.0f * x, -2.0f * y, -2.0f * z,
                                       x * x + y * y + z * z);
}

__device__ __forceinline__ void scan_cell(const float4* __restrict__ tgt,
                                          const int* __restrict__ starts,
                                          int cell, float qx, float qy, float qz,
                                          float& m) {
    int j = starts[cell], e = starts[cell + 1];
    for (; j < e; j++) {
        float4 B = tgt[j];
        float d = fmaf(qz, B.z, fmaf(qy, B.y, fmaf(qx, B.x, B.w)));
        m = fminf(m, d);
    }
}

__global__ __launch_bounds__(256)
void cd_query_kernel() {
    Box bx = load_box();
    const int t = blockIdx.x * blockDim.x + threadIdx.x;   // 0 .. 2*NPTS-1
    const int dir = t >> 14;                               // queries cloud
    const int s = t & (NPTS - 1);
    const float4* __restrict__ tgt = g_sorted[dir ^ 1];
    const int*    __restrict__ st  = g_starts[dir ^ 1];

    float4 A = g_sorted[dir][s];
    float qx = -0.5f * A.x, qy = -0.5f * A.y, qz = -0.5f * A.z;
    float an = A.w;

    int cx = cell1(qx, bx.lox, bx.icx);
    int cy = cell1(qy, bx.loy, bx.icy);
    int cz = cell1(qz, bx.loz, bx.icz);

    float m = 3.4e38f;

    // r = 1 cube (27 cells, clamped)
    {
        int z0 = max(cz - 1, 0), z1 = min(cz + 1, G - 1);
        int y0 = max(cy - 1, 0), y1 = min(cy + 1, G - 1);
        int x0 = max(cx - 1, 0), x1 = min(cx + 1, G - 1);
        for (int z = z0; z <= z1; z++)
            for (int y = y0; y <= y1; y++) {
                int rowbase = (z * G + y) * G;
                for (int x = x0; x <= x1; x++)
                    scan_cell(tgt, st, rowbase + x, qx, qy, qz, m);
            }
    }

    // expand shells until guaranteed
    int r = 1;
    while (r < G) {
        float bound = (float)r * bx.csmin;
        if (fmaxf(m + an, 0.0f) <= bound * bound) break;
        r++;
        for (int dz = -r; dz <= r; dz++) {
            int z = cz + dz;
            if (z < 0 || z >= G) continue;
            int adz = abs(dz);
            for (int dy = -r; dy <= r; dy++) {
                int y = cy + dy;
                if (y < 0 || y >= G) continue;
                int rowbase = (z * G + y) * G;
                if (max(adz, abs(dy)) == r) {
                    int x0 = max(cx - r, 0), x1 = min(cx + r, G - 1);
                    for (int x = x0; x <= x1; x++)
                        scan_cell(tgt, st, rowbase + x, qx, qy, qz, m);
                } else {
                    if (cx - r >= 0)    scan_cell(tgt, st, rowbase + cx - r, qx, qy, qz, m);
                    if (cx + r <= G - 1) scan_cell(tgt, st, rowbase + cx + r, qx, qy, qz, m);
                }
            }
        }
    }

    g_dmin[t] = fmaxf(m + an, 0.0f);
}

__global__ __launch_bounds__(256)
void cd_reduce_kernel(float* __restrict__ out) {
    __shared__ double ssum[256];
    double s = 0.0;
    for (int i = threadIdx.x; i < 2 * NPTS; i += 256)
        s += (double)g_dmin[i];
    ssum[threadIdx.x] = s;
    __syncthreads();
    for (int st = 128; st > 0; st >>= 1) {
        if (threadIdx.x < st) ssum[threadIdx.x] += ssum[threadIdx.x + st];
        __syncthreads();
    }
    if (threadIdx.x == 0)
        out[0] = (float)(ssum[0] / (double)NPTS);  // mean1 + mean2
}

extern "C" void kernel_launch(void* const* d_in, const int* in_sizes, int n_in,
                              void* d_out, int out_size) {
    const float* gt  = (const float*)d_in[0];
    const float* gen = (const float*)d_in[1];
    float* out = (float*)d_out;

    cd_init_kernel   <<<(2 * NC + 255) / 256, 256>>>();
    cd_bbox_kernel   <<<(2 * NPTS) / 256, 256>>>(gt, gen);
    cd_hist_kernel   <<<(2 * NPTS) / 256, 256>>>(gt, gen);
    cd_scan_kernel   <<<2, 1024>>>();
    cd_scatter_kernel<<<(2 * NPTS) / 256, 256>>>(gt, gen);
    cd_query_kernel  <<<(2 * NPTS) / 256, 256>>>();
    cd_reduce_kernel <<<1, 256>>>(out);
}

// round 4
// speedup vs baseline: 2.1009x; 2.1009x over previous
#include <cuda_runtime.h>
#include <cuda_bf16.h>
#include <cstdint>

// Chamfer distance via exact uniform-grid nearest neighbor (G=32^3 cells).
// bbox+clear -> histogram -> fast CSR scan -> scatter (cell-sorted float4
// {-2x,-2y,-2z,|p|^2} + original index) -> row-range ring-search query ->
// deterministic reduce. Exactness: after scanning the Chebyshev radius-r cell
// cube, every unscanned point is >= r*cs_min away; expand until best <= bound.

#define NPTS    16384
#define G       32
#define NC      (G * G * G)
#define NCP     (NC + 8)            // padded row so cloud-1 starts stay 16B-aligned

typedef unsigned int u32;

// ---------------- scratch (__device__ globals; no allocs) ----------------
__device__ u32    g_bbox[6] = {0xFFFFFFFFu, 0xFFFFFFFFu, 0xFFFFFFFFu, 0u, 0u, 0u};
__device__ int    g_counts[2][NC];
__device__ int    g_starts[2][NCP];         // [cloud][cell], sentinel at [cloud][NC]
__device__ int    g_cursor[2][NC];
__device__ float4 g_sorted[2][NPTS];        // cell-sorted, preprocessed
__device__ int    g_oidx[2][NPTS];          // original index of sorted point
__device__ float  g_dmin[2 * NPTS];         // indexed by ORIGINAL index (deterministic)

// ---------------- helpers ----------------
__device__ __forceinline__ u32 flip_enc(float x) {
    u32 u = __float_as_uint(x);
    return u ^ ((u & 0x80000000u) ? 0xFFFFFFFFu : 0x80000000u);
}
__device__ __forceinline__ float flip_dec(u32 u) {
    u ^= (u & 0x80000000u) ? 0x80000000u : 0xFFFFFFFFu;
    return __uint_as_float(u);
}

struct Box { float lox, loy, loz, icx, icy, icz, csmin; };

__device__ __forceinline__ Box load_box() {
    Box b;
    b.lox = flip_dec(g_bbox[0]);
    b.loy = flip_dec(g_bbox[1]);
    b.loz = flip_dec(g_bbox[2]);
    float ex = fmaxf(flip_dec(g_bbox[3]) - b.lox, 1e-6f);
    float ey = fmaxf(flip_dec(g_bbox[4]) - b.loy, 1e-6f);
    float ez = fmaxf(flip_dec(g_bbox[5]) - b.loz, 1e-6f);
    float csx = ex / G, csy = ey / G, csz = ez / G;
    b.icx = 1.0f / csx; b.icy = 1.0f / csy; b.icz = 1.0f / csz;
    b.csmin = fminf(csx, fminf(csy, csz));
    return b;
}
__device__ __forceinline__ int clampi(int v, int lo, int hi) {
    return v < lo ? lo : (v > hi ? hi : v);
}
__device__ __forceinline__ int cell1(float v, float lo, float ic) {
    return clampi((int)floorf((v - lo) * ic), 0, G - 1);
}

// ---------------- K1: clear counts + bbox reduction (merged) ----------------
__global__ __launch_bounds__(256)
void cd_init_bbox_kernel(const float* __restrict__ gt, const float* __restrict__ gen) {
    __shared__ u32 smn[3][8], smx[3][8];
    const int t = blockIdx.x * blockDim.x + threadIdx.x;   // 0 .. 2*NPTS-1
    ((int*)g_counts)[t] = 0;
    ((int*)g_counts)[t + 2 * NPTS] = 0;

    const float* p = (t < NPTS) ? (gt + 3 * t) : (gen + 3 * (t - NPTS));
    u32 ex = flip_enc(p[0]), ey = flip_enc(p[1]), ez = flip_enc(p[2]);
    u32 mx = ex, my = ey, mz = ez;
#pragma unroll
    for (int s = 16; s > 0; s >>= 1) {
        ex = min(ex, __shfl_xor_sync(0xFFFFFFFFu, ex, s));
        ey = min(ey, __shfl_xor_sync(0xFFFFFFFFu, ey, s));
        ez = min(ez, __shfl_xor_sync(0xFFFFFFFFu, ez, s));
        mx = max(mx, __shfl_xor_sync(0xFFFFFFFFu, mx, s));
        my = max(my, __shfl_xor_sync(0xFFFFFFFFu, my, s));
        mz = max(mz, __shfl_xor_sync(0xFFFFFFFFu, mz, s));
    }
    int wid = threadIdx.x >> 5, lid = threadIdx.x & 31;
    if (lid == 0) {
        smn[0][wid] = ex; smn[1][wid] = ey; smn[2][wid] = ez;
        smx[0][wid] = mx; smx[1][wid] = my; smx[2][wid] = mz;
    }
    __syncthreads();
    if (threadIdx.x < 3) {
        u32 a = 0xFFFFFFFFu, b = 0u;
#pragma unroll
        for (int w = 0; w < 8; w++) { a = min(a, smn[threadIdx.x][w]); b = max(b, smx[threadIdx.x][w]); }
        atomicMin(&g_bbox[threadIdx.x], a);       // idempotent across graph replays
        atomicMax(&g_bbox[threadIdx.x + 3], b);
    }
}

// ---------------- K2: histogram ----------------
__global__ __launch_bounds__(256)
void cd_hist_kernel(const float* __restrict__ gt, const float* __restrict__ gen) {
    Box bx = load_box();
    int t = blockIdx.x * blockDim.x + threadIdx.x;
    int cloud = t >> 14, i = t & (NPTS - 1);
    const float* p = (cloud == 0 ? gt : gen) + 3 * i;
    int cx = cell1(p[0], bx.lox, bx.icx);
    int cy = cell1(p[1], bx.loy, bx.icy);
    int cz = cell1(p[2], bx.loz, bx.icz);
    atomicAdd(&g_counts[cloud][(cz * G + cy) * G + cx], 1);
}

// ---------------- K3: CSR scan (one CTA per cloud, int4 vector I/O) ----------------
__global__ __launch_bounds__(1024)
void cd_scan_kernel() {
    __shared__ int part[1024];
    const int cloud = blockIdx.x;
    const int tid = threadIdx.x;

    int4 v[8];
    const int4* src = (const int4*)(g_counts[cloud] + tid * 32);
#pragma unroll
    for (int i = 0; i < 8; i++) v[i] = src[i];          // 8-deep MLP

    int s = 0;
#pragma unroll
    for (int i = 0; i < 8; i++) s += v[i].x + v[i].y + v[i].z + v[i].w;
    part[tid] = s;
    __syncthreads();
    for (int st = 1; st < 1024; st <<= 1) {
        int t2 = (tid >= st) ? part[tid - st] : 0;
        __syncthreads();
        part[tid] += t2;
        __syncthreads();
    }
    int run = (tid == 0) ? 0 : part[tid - 1];           // exclusive prefix of chunk
#pragma unroll
    for (int i = 0; i < 8; i++) {
        int a = v[i].x, b = v[i].y, c = v[i].z, d = v[i].w;
        v[i].x = run; v[i].y = run + a; v[i].z = run + a + b; v[i].w = run + a + b + c;
        run += a + b + c + d;
    }
    int4* dst = (int4*)(g_starts[cloud] + tid * 32);
    int4* cur = (int4*)(g_cursor[cloud] + tid * 32);
#pragma unroll
    for (int i = 0; i < 8; i++) { dst[i] = v[i]; cur[i] = v[i]; }
    if (tid == 1023) g_starts[cloud][NC] = run;         // == NPTS sentinel
}

// ---------------- K4: scatter into cell-sorted order ----------------
__global__ __launch_bounds__(256)
void cd_scatter_kernel(const float* __restrict__ gt, const float* __restrict__ gen) {
    Box bx = load_box();
    int t = blockIdx.x * blockDim.x + threadIdx.x;
    int cloud = t >> 14, i = t & (NPTS - 1);
    const float* p = (cloud == 0 ? gt : gen) + 3 * i;
    float x = p[0], y = p[1], z = p[2];
    int cx = cell1(x, bx.lox, bx.icx);
    int cy = cell1(y, bx.loy, bx.icy);
    int cz = cell1(z, bx.loz, bx.icz);
    int pos = atomicAdd(&g_cursor[cloud][(cz * G + cy) * G + cx], 1);
    g_sorted[cloud][pos] = make_float4(-2.0f * x, -2.0f * y, -2.0f * z,
                                       x * x + y * y + z * z);
    g_oidx[cloud][pos] = i;
}

// ---------------- K5: ring-search query ----------------
__device__ __forceinline__ void scan_range(const float4* __restrict__ tgt,
                                           int j, int e,
                                           float qx, float qy, float qz, float& m) {
    for (; j < e; j++) {
        float4 B = __ldg(&tgt[j]);
        float d = fmaf(qz, B.z, fmaf(qy, B.y, fmaf(qx, B.x, B.w)));
        m = fminf(m, d);
    }
}

__global__ __launch_bounds__(256)
void cd_query_kernel() {
    Box bx = load_box();
    const int t = blockIdx.x * blockDim.x + threadIdx.x;   // 0 .. 2*NPTS-1
    const int dir = t >> 14;
    const int s = t & (NPTS - 1);
    const float4* __restrict__ tgt = g_sorted[dir ^ 1];
    const int*    __restrict__ st  = g_starts[dir ^ 1];

    float4 A = g_sorted[dir][s];                           // cell-coherent within warp
    const int oi = g_oidx[dir][s];
    float qx = -0.5f * A.x, qy = -0.5f * A.y, qz = -0.5f * A.z;
    float an = A.w;

    int cx = cell1(qx, bx.lox, bx.icx);
    int cy = cell1(qy, bx.loy, bx.icy);
    int cz = cell1(qz, bx.loz, bx.icz);

    float m = 3.4e38f;

    // r = 1 cube: 3x3 merged x-row ranges
    {
        int x0 = max(cx - 1, 0), x1 = min(cx + 1, G - 1);
        int z0 = max(cz - 1, 0), z1 = min(cz + 1, G - 1);
        int y0 = max(cy - 1, 0), y1 = min(cy + 1, G - 1);
        for (int z = z0; z <= z1; z++)
            for (int y = y0; y <= y1; y++) {
                int rb = (z * G + y) * G;
                scan_range(tgt, st[rb + x0], st[rb + x1 + 1], qx, qy, qz, m);
            }
    }

    // expand shells until the ring bound certifies the min
    int r = 1;
    while (r < G) {
        float bound = (float)r * bx.csmin;
        if (m + an <= bound * bound) break;
        r++;
        int x0 = max(cx - r, 0), x1 = min(cx + r, G - 1);
        for (int dz = -r; dz <= r; dz++) {
            int z = cz + dz;
            if ((unsigned)z >= G) continue;
            int adz = abs(dz);
            for (int dy = -r; dy <= r; dy++) {
                int y = cy + dy;
                if ((unsigned)y >= G) continue;
                int rb = (z * G + y) * G;
                if (max(adz, abs(dy)) == r) {
                    scan_range(tgt, st[rb + x0], st[rb + x1 + 1], qx, qy, qz, m);
                } else {
                    if (cx - r >= 0)
                        scan_range(tgt, st[rb + cx - r], st[rb + cx - r + 1], qx, qy, qz, m);
                    if (cx + r <= G - 1)
                        scan_range(tgt, st[rb + cx + r], st[rb + cx + r + 1], qx, qy, qz, m);
                }
            }
        }
    }

    g_dmin[dir * NPTS + oi] = fmaxf(m + an, 0.0f);         // deterministic slot
}

// ---------------- K6: deterministic reduce ----------------
__global__ __launch_bounds__(256)
void cd_reduce_kernel(float* __restrict__ out) {
    __shared__ double ssum[256];
    double s = 0.0;
    for (int i = threadIdx.x; i < 2 * NPTS; i += 256)
        s += (double)g_dmin[i];
    ssum[threadIdx.x] = s;
    __syncthreads();
    for (int st = 128; st > 0; st >>= 1) {
        if (threadIdx.x < st) ssum[threadIdx.x] += ssum[threadIdx.x + st];
        __syncthreads();
    }
    if (threadIdx.x == 0)
        out[0] = (float)(ssum[0] / (double)NPTS);          // mean1 + mean2
}

extern "C" void kernel_launch(void* const* d_in, const int* in_sizes, int n_in,
                              void* d_out, int out_size) {
    const float* gt  = (const float*)d_in[0];
    const float* gen = (const float*)d_in[1];
    float* out = (float*)d_out;

    cd_init_bbox_kernel<<<(2 * NPTS) / 256, 256>>>(gt, gen);
    cd_hist_kernel     <<<(2 * NPTS) / 256, 256>>>(gt, gen);
    cd_scan_kernel     <<<2, 1024>>>();
    cd_scatter_kernel  <<<(2 * NPTS) / 256, 256>>>(gt, gen);
    cd_query_kernel    <<<(2 * NPTS) / 256, 256>>>();
    cd_reduce_kernel   <<<1, 256>>>(out);
}

// round 6
// speedup vs baseline: 2.1860x; 1.0405x over previous
#include <cuda_runtime.h>
#include <cstdint>

// Chamfer distance: ONE persistent kernel (128 co-resident CTAs, device-wide
// sense-reversing barriers). 32768 threads = one (cloud,point) pair per thread
// = one cell per thread per cloud in the scan phase. Fixed grid box [-B,B]^3,
// G=32 (exact even for clamped outliers: cells at Chebyshev index distance
// >= r+1 are >= r*cs apart in real space).
// Phases: hist+stage -> CTA-local CSR scan -> offsets+starts+cursor(+re-zero
// counts for next replay) -> scatter -> ring-search query with fixed-point
// (x 2^32) u64 sum (permutation-invariant => deterministic) -> finalize.

#define NPTS   16384
#define G      32
#define NC     (G * G * G)          // 32768
#define NCTA   128
#define NTHR   256
#define BOXB   4.8f
#define CS     (2.0f * BOXB / (float)G)   // 0.3
#define INV_CS (1.0f / CS)

typedef unsigned long long u64;

// ---------- scratch (__device__ globals; zero-initialized at load) ----------
__device__ int    g_counts[2][NC];     // re-zeroed each execution for the next
__device__ int    g_starts[2][NC + 1];
__device__ int    g_cursor[2][NC];
__device__ int    g_part[2][NCTA];
__device__ float4 g_pre[2][NPTS];      // staged {-2x,-2y,-2z,|p|^2}
__device__ int    g_cellid[2][NPTS];
__device__ float4 g_sorted[2][NPTS];
__device__ u64    g_sum;               // fixed-point total; reset each execution
__device__ int    g_bar_cnt;           // barrier state (self-resetting)
__device__ int    g_bar_sense;

// ---------- device-wide barrier ----------
__device__ __forceinline__ int ld_acq(const int* p) {
    int v; asm volatile("ld.acquire.gpu.b32 %0, [%1];" : "=r"(v) : "l"(p)); return v;
}
__device__ __forceinline__ void st_rel(int* p, int v) {
    asm volatile("st.release.gpu.b32 [%0], %1;" :: "l"(p), "r"(v) : "memory");
}
__device__ __forceinline__ void grid_bar(int& sense) {
    __syncthreads();
    if (threadIdx.x == 0) {
        int target = sense ^ 1;
        __threadfence();
        int a = atomicAdd(&g_bar_cnt, 1);
        if (a == NCTA - 1) {
            atomicExch(&g_bar_cnt, 0);       // reset BEFORE release
            st_rel(&g_bar_sense, target);
        } else {
            while (ld_acq(&g_bar_sense) != target) __nanosleep(32);
        }
        __threadfence();
    }
    sense ^= 1;
    __syncthreads();
}

__device__ __forceinline__ int cell1(float v) {
    int c = (int)floorf((v + BOXB) * INV_CS);
    return c < 0 ? 0 : (c > G - 1 ? G - 1 : c);
}

__device__ __forceinline__ void scan_range(const float4* __restrict__ tgt,
                                           int j, int e,
                                           float qx, float qy, float qz, float& m) {
    for (; j < e; j++) {
        float4 B = __ldg(&tgt[j]);
        float d = fmaf(qz, B.z, fmaf(qy, B.y, fmaf(qx, B.x, B.w)));
        m = fminf(m, d);
    }
}

__global__ __launch_bounds__(NTHR)
void cd_fused_kernel(const float* __restrict__ gt, const float* __restrict__ gen,
                     float* __restrict__ out) {
    __shared__ int sc[NTHR];
    __shared__ int s_off[2];

    const int tid   = threadIdx.x;
    const int t     = blockIdx.x * NTHR + tid;      // 0 .. 2*NPTS-1
    const int cloud = t >> 14;                      // which cloud this thread owns
    const int i     = t & (NPTS - 1);               // point index within cloud
    int sense = ld_acq(&g_bar_sense);               // stable before first barrier

    // ---- P1: histogram + stage preprocessed point (one per thread) ----
    {
        const float* p = (cloud == 0 ? gt : gen) + 3 * i;
        float x = p[0], y = p[1], z = p[2];
        int cell = (cell1(z) * G + cell1(y)) * G + cell1(x);
        atomicAdd(&g_counts[cloud][cell], 1);
        g_pre[cloud][i]    = make_float4(-2.0f * x, -2.0f * y, -2.0f * z,
                                         x * x + y * y + z * z);
        g_cellid[cloud][i] = cell;
    }
    grid_bar(sense);                                // GB1

    // ---- P2a: CTA-local scan of this CTA's 256-cell chunk (per cloud) ----
    const int cidx = blockIdx.x * NTHR + tid;       // cell index: covers all NC
    int excl[2];
#pragma unroll
    for (int c = 0; c < 2; c++) {
        int cnt = g_counts[c][cidx];
        sc[tid] = cnt;
        __syncthreads();
        for (int st = 1; st < NTHR; st <<= 1) {
            int v = (tid >= st) ? sc[tid - st] : 0;
            __syncthreads();
            sc[tid] += v;
            __syncthreads();
        }
        excl[c] = sc[tid] - cnt;
        if (tid == NTHR - 1) g_part[c][blockIdx.x] = sc[tid];
        __syncthreads();
    }
    grid_bar(sense);                                // GB2

    // ---- P2b: global offset (masked sum of parts < my CTA), then publish ----
    if (tid < 32) {
#pragma unroll
        for (int c = 0; c < 2; c++) {
            int acc = 0;
#pragma unroll
            for (int k = 0; k < NCTA / 32; k++) {
                int idx = k * 32 + tid;
                int pv = g_part[c][idx];
                if (idx < blockIdx.x) acc += pv;
            }
#pragma unroll
            for (int s = 16; s > 0; s >>= 1)
                acc += __shfl_xor_sync(0xFFFFFFFFu, acc, s);
            if (tid == 0) s_off[c] = acc;
        }
    }
    __syncthreads();
#pragma unroll
    for (int c = 0; c < 2; c++) {
        int s = s_off[c] + excl[c];
        g_starts[c][cidx] = s;
        g_cursor[c][cidx] = s;
        g_counts[c][cidx] = 0;                      // re-zero for next replay
    }
    if (blockIdx.x == NCTA - 1 && tid == NTHR - 1) {
        g_starts[0][NC] = NPTS;
        g_starts[1][NC] = NPTS;
    }
    grid_bar(sense);                                // GB3

    // ---- P3: scatter into cell-sorted order (one point per thread) ----
    {
        int cell = g_cellid[cloud][i];
        int pos  = atomicAdd(&g_cursor[cloud][cell], 1);
        g_sorted[cloud][pos] = g_pre[cloud][i];
    }
    grid_bar(sense);                                // GB4

    // ---- P4: ring-search query (one query per thread), fixed-point sum ----
    u64 acc;
    {
        const int dir = cloud;                      // this thread queries its cloud
        const float4* __restrict__ tgt = g_sorted[dir ^ 1];
        const int*    __restrict__ st  = g_starts[dir ^ 1];

        float4 A = g_sorted[dir][i];                // cell-coherent within warp
        float qx = -0.5f * A.x, qy = -0.5f * A.y, qz = -0.5f * A.z;
        float an = A.w;
        int cx = cell1(qx), cy = cell1(qy), cz = cell1(qz);

        float m = 3.4e38f;
        {   // r = 1 cube: merged x-row ranges
            int x0 = max(cx - 1, 0), x1 = min(cx + 1, G - 1);
            int z0 = max(cz - 1, 0), z1 = min(cz + 1, G - 1);
            int y0 = max(cy - 1, 0), y1 = min(cy + 1, G - 1);
            for (int z = z0; z <= z1; z++)
                for (int y = y0; y <= y1; y++) {
                    int rb = (z * G + y) * G;
                    scan_range(tgt, st[rb + x0], st[rb + x1 + 1], qx, qy, qz, m);
                }
        }
        int r = 1;
        while (r < G) {                             // expand until certified
            float bound = (float)r * CS;
            if (m + an <= bound * bound) break;
            r++;
            int x0 = max(cx - r, 0), x1 = min(cx + r, G - 1);
            for (int dz = -r; dz <= r; dz++) {
                int z = cz + dz;
                if ((unsigned)z >= G) continue;
                int adz = abs(dz);
                for (int dy = -r; dy <= r; dy++) {
                    int y = cy + dy;
                    if ((unsigned)y >= G) continue;
                    int rb = (z * G + y) * G;
                    if (max(adz, abs(dy)) == r) {
                        scan_range(tgt, st[rb + x0], st[rb + x1 + 1], qx, qy, qz, m);
                    } else {
                        if (cx - r >= 0)
                            scan_range(tgt, st[rb + cx - r], st[rb + cx - r + 1], qx, qy, qz, m);
                        if (cx + r <= G - 1)
                            scan_range(tgt, st[rb + cx + r], st[rb + cx + r + 1], qx, qy, qz, m);
                    }
                }
            }
        }
        float d = fmaxf(m + an, 0.0f);
        acc = (u64)((double)d * 4294967296.0);      // x 2^32 fixed point
    }
    // warp reduce + one RED per warp (integer => order-invariant, deterministic)
#pragma unroll
    for (int s = 16; s > 0; s >>= 1)
        acc += __shfl_down_sync(0xFFFFFFFFu, acc, s);
    if ((tid & 31) == 0) atomicAdd(&g_sum, acc);
    grid_bar(sense);                                // GB5

    // ---- P5: finalize + reset accumulator for next replay ----
    if (blockIdx.x == 0 && tid == 0) {
        double s = (double)g_sum * (1.0 / 4294967296.0);
        out[0] = (float)(s / (double)NPTS);         // mean1 + mean2
        g_sum = 0ull;
    }
}

extern "C" void kernel_launch(void* const* d_in, const int* in_sizes, int n_in,
                              void* d_out, int out_size) {
    const float* gt  = (const float*)d_in[0];
    const float* gen = (const float*)d_in[1];
    float* out = (float*)d_out;
    cd_fused_kernel<<<NCTA, NTHR>>>(gt, gen, out);
}